// round 15
// baseline (speedup 1.0000x reference)
#include <cuda_runtime.h>

// H=1080, W=1920 (n_pix = 2,073,600, /4 ok), S=2000, C=8.
// Output (float32): [1,1,H,W] preseg then [7,4,H,W] attmaps, flattened.
//
// R9 design (grid-stride, measured best) + label prefetch + warp-rotated
// plane store order. Full precomputed table in smem: S x 28 floats + S pred.

#define NCLS 8
#define NJ   7

__global__ __launch_bounds__(1024, 1)
void fused_scatter_kernel(const int* __restrict__ spx,
                          const int* __restrict__ pred,
                          const float* __restrict__ knn,
                          const float* __restrict__ cent,
                          float* __restrict__ out,
                          int S, int n4, int n_pix)
{
    extern __shared__ float smem[];
    float* att = smem;                       // S rows x 28 floats (112 B)
    float* prd = smem + (size_t)S * 28;      // S floats

    const float NEG_INF = -__int_as_float(0x7f800000);

    // ---- Phase 1: build precomputed table in smem ----
    for (int s = threadIdx.x; s < S; s += blockDim.x) {
        float4 k0 = __ldg((const float4*)knn  + (size_t)s * 2);
        float4 k1 = __ldg((const float4*)knn  + (size_t)s * 2 + 1);
        float4 c0 = __ldg((const float4*)cent + (size_t)s * 2);
        float4 c1 = __ldg((const float4*)cent + (size_t)s * 2 + 1);
        float k[NCLS] = {k0.x, k0.y, k0.z, k0.w, k1.x, k1.y, k1.z, k1.w};
        float c[NCLS] = {c0.x, c0.y, c0.z, c0.w, c1.x, c1.y, c1.z, c1.w};

        float km1 = k[0], km2 = NEG_INF; int ka = 0;
#pragma unroll
        for (int j = 1; j < NCLS; j++) {
            if (k[j] > km1)      { km2 = km1; km1 = k[j]; ka = j; }
            else if (k[j] > km2) { km2 = k[j]; }
        }
        float cm1 = c[0], cm2 = NEG_INF; int ca = 0;
#pragma unroll
        for (int j = 1; j < NCLS; j++) {
            if (c[j] > cm1)      { cm2 = cm1; cm1 = c[j]; ca = j; }
            else if (c[j] > cm2) { cm2 = c[j]; }
        }

        float4* row = (float4*)(att + (size_t)s * 28);
#pragma unroll
        for (int jj = 0; jj < NJ; jj++) {
            int j = jj + 1;
            row[jj] = make_float4(k[j], (j == ka) ? km2 : km1,
                                  c[j], (j == ca) ? cm2 : cm1);
        }
        prd[s] = (float)__ldg(pred + s);
    }
    __syncthreads();

    // ---- Phase 2: grid-stride, 4 pixels/thread, prefetched labels,
    //      per-warp rotated plane order ----
    int rot = (threadIdx.x >> 5) % NJ;       // warp's starting plane group
    int stride = gridDim.x * blockDim.x;
    int t = blockIdx.x * blockDim.x + threadIdx.x;
    if (t >= n4) return;

    int4 lab = __ldcs((const int4*)spx + t);
    for (; t < n4; t += stride) {
        int tn = t + stride;
        int4 labn = (tn < n4) ? __ldcs((const int4*)spx + tn) : lab;

        const float4* r0 = (const float4*)(att + (size_t)(lab.x - 1) * 28);
        const float4* r1 = (const float4*)(att + (size_t)(lab.y - 1) * 28);
        const float4* r2 = (const float4*)(att + (size_t)(lab.z - 1) * 28);
        const float4* r3 = (const float4*)(att + (size_t)(lab.w - 1) * 28);

        size_t p = (size_t)t * 4;

        // preseg plane
        __stcs((float4*)(out + p),
               make_float4(prd[lab.x - 1], prd[lab.y - 1],
                           prd[lab.z - 1], prd[lab.w - 1]));

        // 28 attmap planes, plane-group order rotated per warp
        float* base = out + (size_t)n_pix + p;
#pragma unroll
        for (int gg = 0; gg < NJ; gg++) {
            int g = gg + rot;
            if (g >= NJ) g -= NJ;
            float4 a  = r0[g];
            float4 b  = r1[g];
            float4 cc = r2[g];
            float4 d  = r3[g];
            float* q = base + (size_t)(4 * g) * n_pix;
            __stcs((float4*)q,                       make_float4(a.x, b.x, cc.x, d.x));
            __stcs((float4*)(q + (size_t)n_pix),     make_float4(a.y, b.y, cc.y, d.y));
            __stcs((float4*)(q + (size_t)2 * n_pix), make_float4(a.z, b.z, cc.z, d.z));
            __stcs((float4*)(q + (size_t)3 * n_pix), make_float4(a.w, b.w, cc.w, d.w));
        }

        lab = labn;
    }
}

extern "C" void kernel_launch(void* const* d_in, const int* in_sizes, int n_in,
                              void* d_out, int out_size) {
    const int*   spx  = (const int*)d_in[0];
    const int*   pred = (const int*)d_in[1];
    const float* knn  = (const float*)d_in[2];
    const float* cent = (const float*)d_in[3];
    float* out = (float*)d_out;

    int n_pix = in_sizes[0];   // 2,073,600
    int S     = in_sizes[1];   // 2000
    int n4    = n_pix / 4;

    size_t smem_bytes = (size_t)S * 29 * sizeof(float);  // 232,000 B

    cudaFuncSetAttribute(fused_scatter_kernel,
                         cudaFuncAttributeMaxDynamicSharedMemorySize,
                         (int)smem_bytes);

    int nsm = 148;
    cudaDeviceGetAttribute(&nsm, cudaDevAttrMultiProcessorCount, 0);

    fused_scatter_kernel<<<nsm, 1024, smem_bytes>>>(
        spx, pred, knn, cent, out, S, n4, n_pix);
}

// round 16
// speedup vs baseline: 1.0707x; 1.0707x over previous
#include <cuda_runtime.h>

// H=1080, W=1920 (n_pix = 2,073,600, /4 ok), S=2000, C=8.
// Output (float32): [1,1,H,W] preseg then [7,4,H,W] attmaps, flattened.
//
// R9 design (grid-stride, 4 px/thread, full precomputed smem table) with
// write-back stores (no .cs): the output buffer is rewritten every graph
// replay, so lines retained dirty in the 126 MB L2 become write hits and
// never cost DRAM bandwidth. spx via __ldg for the same L2-residency reason.

#define NCLS 8
#define NJ   7

__global__ __launch_bounds__(1024, 1)
void fused_scatter_kernel(const int* __restrict__ spx,
                          const int* __restrict__ pred,
                          const float* __restrict__ knn,
                          const float* __restrict__ cent,
                          float* __restrict__ out,
                          int S, int n4, int n_pix)
{
    extern __shared__ float smem[];
    float* att = smem;                       // S rows x 28 floats (112 B)
    float* prd = smem + (size_t)S * 28;      // S floats

    const float NEG_INF = -__int_as_float(0x7f800000);

    // ---- Phase 1: build precomputed table in smem ----
    for (int s = threadIdx.x; s < S; s += blockDim.x) {
        float4 k0 = __ldg((const float4*)knn  + (size_t)s * 2);
        float4 k1 = __ldg((const float4*)knn  + (size_t)s * 2 + 1);
        float4 c0 = __ldg((const float4*)cent + (size_t)s * 2);
        float4 c1 = __ldg((const float4*)cent + (size_t)s * 2 + 1);
        float k[NCLS] = {k0.x, k0.y, k0.z, k0.w, k1.x, k1.y, k1.z, k1.w};
        float c[NCLS] = {c0.x, c0.y, c0.z, c0.w, c1.x, c1.y, c1.z, c1.w};

        float km1 = k[0], km2 = NEG_INF; int ka = 0;
#pragma unroll
        for (int j = 1; j < NCLS; j++) {
            if (k[j] > km1)      { km2 = km1; km1 = k[j]; ka = j; }
            else if (k[j] > km2) { km2 = k[j]; }
        }
        float cm1 = c[0], cm2 = NEG_INF; int ca = 0;
#pragma unroll
        for (int j = 1; j < NCLS; j++) {
            if (c[j] > cm1)      { cm2 = cm1; cm1 = c[j]; ca = j; }
            else if (c[j] > cm2) { cm2 = c[j]; }
        }

        float4* row = (float4*)(att + (size_t)s * 28);
#pragma unroll
        for (int jj = 0; jj < NJ; jj++) {
            int j = jj + 1;
            row[jj] = make_float4(k[j], (j == ka) ? km2 : km1,
                                  c[j], (j == ca) ? cm2 : cm1);
        }
        prd[s] = (float)__ldg(pred + s);
    }
    __syncthreads();

    // ---- Phase 2: grid-stride, 4 pixels/thread, smem gathers, WB stores ----
    int stride = gridDim.x * blockDim.x;
    for (int t = blockIdx.x * blockDim.x + threadIdx.x; t < n4; t += stride) {
        int4 lab = __ldg((const int4*)spx + t);
        const float4* r0 = (const float4*)(att + (size_t)(lab.x - 1) * 28);
        const float4* r1 = (const float4*)(att + (size_t)(lab.y - 1) * 28);
        const float4* r2 = (const float4*)(att + (size_t)(lab.z - 1) * 28);
        const float4* r3 = (const float4*)(att + (size_t)(lab.w - 1) * 28);

        size_t p = (size_t)t * 4;

        // preseg plane
        *(float4*)(out + p) = make_float4(prd[lab.x - 1], prd[lab.y - 1],
                                          prd[lab.z - 1], prd[lab.w - 1]);

        // 28 attmap planes
        float* q = out + (size_t)n_pix + p;
#pragma unroll
        for (int g = 0; g < NJ; g++) {
            float4 a  = r0[g];
            float4 b  = r1[g];
            float4 cc = r2[g];
            float4 d  = r3[g];
            *(float4*)q                       = make_float4(a.x, b.x, cc.x, d.x);
            *(float4*)(q + (size_t)n_pix)     = make_float4(a.y, b.y, cc.y, d.y);
            *(float4*)(q + (size_t)2 * n_pix) = make_float4(a.z, b.z, cc.z, d.z);
            *(float4*)(q + (size_t)3 * n_pix) = make_float4(a.w, b.w, cc.w, d.w);
            q += (size_t)4 * n_pix;
        }
    }
}

extern "C" void kernel_launch(void* const* d_in, const int* in_sizes, int n_in,
                              void* d_out, int out_size) {
    const int*   spx  = (const int*)d_in[0];
    const int*   pred = (const int*)d_in[1];
    const float* knn  = (const float*)d_in[2];
    const float* cent = (const float*)d_in[3];
    float* out = (float*)d_out;

    int n_pix = in_sizes[0];   // 2,073,600
    int S     = in_sizes[1];   // 2000
    int n4    = n_pix / 4;

    size_t smem_bytes = (size_t)S * 29 * sizeof(float);  // 232,000 B

    cudaFuncSetAttribute(fused_scatter_kernel,
                         cudaFuncAttributeMaxDynamicSharedMemorySize,
                         (int)smem_bytes);

    int nsm = 148;
    cudaDeviceGetAttribute(&nsm, cudaDevAttrMultiProcessorCount, 0);

    fused_scatter_kernel<<<nsm, 1024, smem_bytes>>>(
        spx, pred, knn, cent, out, S, n4, n_pix);
}

// round 17
// speedup vs baseline: 1.0776x; 1.0064x over previous
#include <cuda_runtime.h>

// H=1080, W=1920 (n_pix = 2,073,600, /4 ok), S=2000, C=8.
// Output (float32): [1,1,H,W] preseg then [7,4,H,W] attmaps, flattened.
//
// R9 design (grid-stride, 4 px/thread, full precomputed smem table) with
// write-back stores (no .cs): the output buffer is rewritten every graph
// replay, so lines retained dirty in the 126 MB L2 become write hits and
// never cost DRAM bandwidth. spx via __ldg for the same L2-residency reason.

#define NCLS 8
#define NJ   7

__global__ __launch_bounds__(1024, 1)
void fused_scatter_kernel(const int* __restrict__ spx,
                          const int* __restrict__ pred,
                          const float* __restrict__ knn,
                          const float* __restrict__ cent,
                          float* __restrict__ out,
                          int S, int n4, int n_pix)
{
    extern __shared__ float smem[];
    float* att = smem;                       // S rows x 28 floats (112 B)
    float* prd = smem + (size_t)S * 28;      // S floats

    const float NEG_INF = -__int_as_float(0x7f800000);

    // ---- Phase 1: build precomputed table in smem ----
    for (int s = threadIdx.x; s < S; s += blockDim.x) {
        float4 k0 = __ldg((const float4*)knn  + (size_t)s * 2);
        float4 k1 = __ldg((const float4*)knn  + (size_t)s * 2 + 1);
        float4 c0 = __ldg((const float4*)cent + (size_t)s * 2);
        float4 c1 = __ldg((const float4*)cent + (size_t)s * 2 + 1);
        float k[NCLS] = {k0.x, k0.y, k0.z, k0.w, k1.x, k1.y, k1.z, k1.w};
        float c[NCLS] = {c0.x, c0.y, c0.z, c0.w, c1.x, c1.y, c1.z, c1.w};

        float km1 = k[0], km2 = NEG_INF; int ka = 0;
#pragma unroll
        for (int j = 1; j < NCLS; j++) {
            if (k[j] > km1)      { km2 = km1; km1 = k[j]; ka = j; }
            else if (k[j] > km2) { km2 = k[j]; }
        }
        float cm1 = c[0], cm2 = NEG_INF; int ca = 0;
#pragma unroll
        for (int j = 1; j < NCLS; j++) {
            if (c[j] > cm1)      { cm2 = cm1; cm1 = c[j]; ca = j; }
            else if (c[j] > cm2) { cm2 = c[j]; }
        }

        float4* row = (float4*)(att + (size_t)s * 28);
#pragma unroll
        for (int jj = 0; jj < NJ; jj++) {
            int j = jj + 1;
            row[jj] = make_float4(k[j], (j == ka) ? km2 : km1,
                                  c[j], (j == ca) ? cm2 : cm1);
        }
        prd[s] = (float)__ldg(pred + s);
    }
    __syncthreads();

    // ---- Phase 2: grid-stride, 4 pixels/thread, smem gathers, WB stores ----
    int stride = gridDim.x * blockDim.x;
    for (int t = blockIdx.x * blockDim.x + threadIdx.x; t < n4; t += stride) {
        int4 lab = __ldg((const int4*)spx + t);
        const float4* r0 = (const float4*)(att + (size_t)(lab.x - 1) * 28);
        const float4* r1 = (const float4*)(att + (size_t)(lab.y - 1) * 28);
        const float4* r2 = (const float4*)(att + (size_t)(lab.z - 1) * 28);
        const float4* r3 = (const float4*)(att + (size_t)(lab.w - 1) * 28);

        size_t p = (size_t)t * 4;

        // preseg plane
        *(float4*)(out + p) = make_float4(prd[lab.x - 1], prd[lab.y - 1],
                                          prd[lab.z - 1], prd[lab.w - 1]);

        // 28 attmap planes
        float* q = out + (size_t)n_pix + p;
#pragma unroll
        for (int g = 0; g < NJ; g++) {
            float4 a  = r0[g];
            float4 b  = r1[g];
            float4 cc = r2[g];
            float4 d  = r3[g];
            *(float4*)q                       = make_float4(a.x, b.x, cc.x, d.x);
            *(float4*)(q + (size_t)n_pix)     = make_float4(a.y, b.y, cc.y, d.y);
            *(float4*)(q + (size_t)2 * n_pix) = make_float4(a.z, b.z, cc.z, d.z);
            *(float4*)(q + (size_t)3 * n_pix) = make_float4(a.w, b.w, cc.w, d.w);
            q += (size_t)4 * n_pix;
        }
    }
}

extern "C" void kernel_launch(void* const* d_in, const int* in_sizes, int n_in,
                              void* d_out, int out_size) {
    const int*   spx  = (const int*)d_in[0];
    const int*   pred = (const int*)d_in[1];
    const float* knn  = (const float*)d_in[2];
    const float* cent = (const float*)d_in[3];
    float* out = (float*)d_out;

    int n_pix = in_sizes[0];   // 2,073,600
    int S     = in_sizes[1];   // 2000
    int n4    = n_pix / 4;

    size_t smem_bytes = (size_t)S * 29 * sizeof(float);  // 232,000 B

    cudaFuncSetAttribute(fused_scatter_kernel,
                         cudaFuncAttributeMaxDynamicSharedMemorySize,
                         (int)smem_bytes);

    int nsm = 148;
    cudaDeviceGetAttribute(&nsm, cudaDevAttrMultiProcessorCount, 0);

    fused_scatter_kernel<<<nsm, 1024, smem_bytes>>>(
        spx, pred, knn, cent, out, S, n4, n_pix);
}